// round 16
// baseline (speedup 1.0000x reference)
#include <cuda_runtime.h>
#include <cuda_fp16.h>
#include <cstdint>

#define NBATCH 2
#define SEQ    1024
#define HID    2048
#define NH     32
#define HD     64

// ======================= scratch =======================
#define QKV_ELEMS ((size_t)NBATCH * NH * SEQ * HD)
__device__ __half g_X[(size_t)NBATCH * SEQ * HID];
__device__ __half g_W[4][(size_t)HID * HID];     // q,k,v,o
__device__ __half g_Q[QKV_ELEMS];                // [b,h,l,d], pre-scaled 1/8
__device__ __half g_K[QKV_ELEMS];                // [b,h,l,d]
__device__ __half g_Vt[QKV_ELEMS];               // [b,h,d,l] transposed
__device__ __half g_O[(size_t)NBATCH * SEQ * HID];

// ======================= helpers =======================
__device__ __forceinline__ uint32_t smem_u32(const void* p) {
    uint32_t a;
    asm("{ .reg .u64 t; cvta.to.shared.u64 t, %1; cvt.u32.u64 %0, t; }"
        : "=r"(a) : "l"(p));
    return a;
}
__device__ __forceinline__ void ldsm_x4(uint32_t* r, uint32_t addr) {
    asm volatile("ldmatrix.sync.aligned.m8n8.x4.shared.b16 {%0,%1,%2,%3}, [%4];"
                 : "=r"(r[0]), "=r"(r[1]), "=r"(r[2]), "=r"(r[3]) : "r"(addr));
}
__device__ __forceinline__ void mma16816(float* c, const uint32_t* a,
                                         const uint32_t* b) {
    asm("mma.sync.aligned.m16n8k16.row.col.f32.f16.f16.f32 "
        "{%0,%1,%2,%3}, {%4,%5,%6,%7}, {%8,%9}, {%0,%1,%2,%3};"
        : "+f"(c[0]), "+f"(c[1]), "+f"(c[2]), "+f"(c[3])
        : "r"(a[0]), "r"(a[1]), "r"(a[2]), "r"(a[3]), "r"(b[0]), "r"(b[1]));
}
__device__ __forceinline__ float fast_sigmoid(float z) {
    float t;
    asm("tanh.approx.f32 %0, %1;" : "=f"(t) : "f"(z * 0.5f));
    return fmaf(0.5f, t, 0.5f);
}
#define CP16(dst, src) \
    asm volatile("cp.async.cg.shared.global [%0], [%1], 16;" \
                 :: "r"(dst), "l"(src) : "memory")
#define CP_COMMIT asm volatile("cp.async.commit_group;" ::: "memory")
#define CP_WAIT0  asm volatile("cp.async.wait_group 0;" ::: "memory")

// ======================= fp32 -> fp16 convert =======================
__global__ void __launch_bounds__(256)
cvt5(const float* __restrict__ X, const float* __restrict__ Wq,
     const float* __restrict__ Wk, const float* __restrict__ Wv,
     const float* __restrict__ Wo) {
    const int z = blockIdx.z;
    const float* src = (z == 0) ? X : (z == 1) ? Wq : (z == 2) ? Wk
                                   : (z == 3) ? Wv : Wo;
    __half* dst = (z == 0) ? g_X : g_W[z - 1];
    size_t i4 = ((size_t)blockIdx.x * 256 + threadIdx.x) * 4;
    float4 v = *(const float4*)(src + i4);
    ushort4 h4;
    h4.x = __half_as_ushort(__float2half_rn(v.x));
    h4.y = __half_as_ushort(__float2half_rn(v.y));
    h4.z = __half_as_ushort(__float2half_rn(v.z));
    h4.w = __half_as_ushort(__float2half_rn(v.w));
    *(ushort4*)(dst + i4) = h4;
}

// ======================= HMMA fp16 GEMM =======================
// C = A @ B^T. CTA 128x128, BK=64, 256 thr / 8 warps of 32x64, 2-stage
// cp.async, 2 CTAs/SM (4 warps/SMSP). B ldsm_x4 spans k32 per n-tile.
// MODE: 0 = fp32 out; 1 = Q scaled 1/8; 2 = K; 3 = V transposed (smem-staged).
#define GSTR  72                 // fp16 elems per smem row = 144B
#define oA    0
#define oB    18432
#define STAGE_BYTES 36864        // A 128*144 + B 128*144
#define GEMM_SMEM (2 * STAGE_BYTES)

template <int MODE>
__device__ __forceinline__ void hmma_gemm_body(
    const __half* __restrict__ A, const __half* __restrict__ B,
    float* __restrict__ Cf, __half* __restrict__ Ch)
{
    extern __shared__ char dsm[];
    const uint32_t sb = smem_u32(dsm);

    const int tid = threadIdx.x;
    const int wid = tid >> 5, lane = tid & 31;
    const int warp_m = (wid >> 1) * 32;      // 0,32,64,96
    const int warp_n = (wid & 1) * 64;       // 0 or 64
    const int m0 = blockIdx.y * 128, n0 = blockIdx.x * 128;

    const uint32_t a_row = (lane & 15);
    const uint32_t a_koff = (lane >> 4) * 8;
    const uint32_t b_row = (lane & 7);
    const uint32_t b_koff = (lane >> 3) * 8; // 0,8,16,24 (k32 span)

    float acc[2][8][4] = {};

    auto load_chunk = [&](int k0, int s) {
        const uint32_t st = sb + s * STAGE_BYTES;
#pragma unroll
        for (int p = 0; p < 4; p++) {        // 128 rows x 8 segs, A and B
            const int flat = p * 256 + tid;
            const int row = flat >> 3, seg = flat & 7;
            const uint32_t so = (uint32_t)(row * 144 + seg * 16);
            CP16(st + oA + so, A + (size_t)(m0 + row) * HID + k0 + seg * 8);
            CP16(st + oB + so, B + (size_t)(n0 + row) * HID + k0 + seg * 8);
        }
    };

    load_chunk(0, 0);
    CP_COMMIT;

    for (int c = 0; c < HID / 64; c++) {
        CP_WAIT0;
        __syncthreads();
        if (c < HID / 64 - 1) {
            load_chunk((c + 1) * 64, (c + 1) & 1);
            CP_COMMIT;
        }
        const uint32_t st = sb + (c & 1) * STAGE_BYTES;

#pragma unroll
        for (int kk = 0; kk < 64; kk += 32) {
            uint32_t bq[8][4];
#pragma unroll
            for (int nt = 0; nt < 8; nt++) {
                const uint32_t off =
                    (uint32_t)((warp_n + nt * 8 + b_row) * GSTR + kk + b_koff) * 2;
                ldsm_x4(bq[nt], st + oB + off);
            }
#pragma unroll
            for (int s = 0; s < 2; s++) {
                uint32_t af[2][4];
#pragma unroll
                for (int mi = 0; mi < 2; mi++) {
                    const uint32_t off =
                        (uint32_t)((warp_m + mi * 16 + a_row) * GSTR +
                                   kk + s * 16 + a_koff) * 2;
                    ldsm_x4(af[mi], st + oA + off);
                }
#pragma unroll
                for (int mi = 0; mi < 2; mi++)
#pragma unroll
                    for (int nt = 0; nt < 8; nt++)
                        mma16816(acc[mi][nt], af[mi], &bq[nt][2 * s]);
            }
        }
    }

    // epilogue
    const int tr = lane >> 2;
    const int tc = (lane & 3) * 2;

    if (MODE == 3) {
        // V: stage transposed tile [n][m] in smem, then coalesced stores.
        __syncthreads();                      // all MMAs done; smem reusable
        __half* stg = (__half*)dsm;           // [128][128] fp16 = 32 KB
#pragma unroll
        for (int mi = 0; mi < 2; mi++) {
#pragma unroll
            for (int ni = 0; ni < 8; ni++) {
                const int col = warp_n + ni * 8 + tc;
#pragma unroll
                for (int half = 0; half < 2; half++) {
                    const int row = warp_m + mi * 16 + half * 8 + tr;
                    stg[col * 128 + row] =
                        __float2half_rn(acc[mi][ni][half * 2]);
                    stg[(col + 1) * 128 + row] =
                        __float2half_rn(acc[mi][ni][half * 2 + 1]);
                }
            }
        }
        __syncthreads();
        const int b = m0 >> 10;
        const int l0 = m0 & (SEQ - 1);
#pragma unroll
        for (int p = 0; p < 8; p++) {         // 128 n-rows x 16 segs of 16B
            const int flat = p * 256 + tid;
            const int nrow = flat >> 4, seg = flat & 15;
            const int h = (n0 + nrow) >> 6, d = (n0 + nrow) & 63;
            *(uint4*)(Ch + (((size_t)b * NH + h) * HD + d) * SEQ + l0 + seg * 8) =
                *(const uint4*)(stg + nrow * 128 + seg * 8);
        }
        return;
    }

#pragma unroll
    for (int mi = 0; mi < 2; mi++) {
#pragma unroll
        for (int ni = 0; ni < 8; ni++) {
            const int col = n0 + warp_n + ni * 8 + tc;
#pragma unroll
            for (int half = 0; half < 2; half++) {
                const int row = m0 + warp_m + mi * 16 + half * 8 + tr;
                float v0 = acc[mi][ni][half * 2];
                float v1 = acc[mi][ni][half * 2 + 1];
                if (MODE == 0) {
                    *(float2*)(Cf + (size_t)row * HID + col) = make_float2(v0, v1);
                } else {
                    const int b = row >> 10, l = row & (SEQ - 1);
                    const int h = col >> 6, d = col & 63;
                    if (MODE == 1) { v0 *= 0.125f; v1 *= 0.125f; }
                    const size_t adr = (((size_t)b * NH + h) * SEQ + l) * HD + d;
                    *(__half2*)(Ch + adr) =
                        __halves2half2(__float2half_rn(v0), __float2half_rn(v1));
                }
            }
        }
    }
}

__global__ void __launch_bounds__(256, 2) qkv_mma() {
    if (blockIdx.z == 0)
        hmma_gemm_body<1>(g_X, g_W[0], nullptr, g_Q);
    else if (blockIdx.z == 1)
        hmma_gemm_body<2>(g_X, g_W[1], nullptr, g_K);
    else
        hmma_gemm_body<3>(g_X, g_W[2], nullptr, g_Vt);
}

__global__ void __launch_bounds__(256, 2) out_mma(float* Out) {
    hmma_gemm_body<0>(g_O, g_W[3], Out, nullptr);
}

// ======================= stick-breaking attention (R11 version) =======================
#define ASTR 72
#define oQ   0
#define oK_  9216
#define oV_  18432
#define oAT  27648
#define oSS  36864               // fp32 [64][66]
#define ATT_SMEM (36864 + 64 * 66 * 4)

__global__ void __launch_bounds__(128, 4) sba_attn()
{
    extern __shared__ char dsm[];
    const uint32_t sb = smem_u32(dsm);

    const int tid = threadIdx.x;
    const int wid = tid >> 5, lane = tid & 31;
    const int warp_m = wid * 16;
    const int ti = (gridDim.x - 1) - blockIdx.x;   // heavy blocks first
    const int bh = blockIdx.y;
    const int i0 = ti * 64;

    const size_t base = (size_t)bh * SEQ * HD;
    const __half* Q_g  = g_Q + base + (size_t)i0 * HD;
    const __half* K_g  = g_K + base;
    const __half* Vt_g = g_Vt + base;              // [d][l]

    // ---- load Q tile (64x64 fp16) ----
#pragma unroll
    for (int t = 0; t < 4; t++) {
        const int flat = t * 128 + tid;
        const int row = flat >> 3, seg = flat & 7;
        const uint32_t off = (uint32_t)(row * 144 + seg * 16);
        CP16(sb + oQ + off, Q_g + row * HD + seg * 8);
    }
    CP_COMMIT;
    CP_WAIT0;
    __syncthreads();

    const uint32_t a_row = lane & 15;
    const uint32_t a_koff = (lane >> 4) * 8;
    const uint32_t b_row = lane & 7;
    const uint32_t b_koff = (lane >> 3) * 8;       // k32 span

    uint32_t qf[4][4];
#pragma unroll
    for (int kk = 0; kk < 4; kk++) {
        const uint32_t off =
            (uint32_t)((warp_m + a_row) * 144 + (kk * 16 + a_koff) * 2);
        ldsm_x4(qf[kk], sb + oQ + off);
    }

    float oacc[8][4] = {};
    float accp = 1.0f;
    const int r = lane >> 2;
    const int c2 = (lane & 3) * 2;

    for (int tj = ti; tj >= 0; tj--) {
        const int j0 = tj * 64;
        __syncthreads();

        // ---- load K [j][d] and Vt [d][j0+j] tiles ----
#pragma unroll
        for (int t = 0; t < 4; t++) {
            const int flat = t * 128 + tid;
            const int row = flat >> 3, seg = flat & 7;
            const uint32_t off = (uint32_t)(row * 144 + seg * 16);
            CP16(sb + oK_ + off, K_g + (size_t)(j0 + row) * HD + seg * 8);
            CP16(sb + oV_ + off, Vt_g + (size_t)row * SEQ + j0 + seg * 8);
        }
        CP_COMMIT;
        CP_WAIT0;
        __syncthreads();

        // ---- z = Q K^T (Q pre-scaled); K x4 spans k32 per n-tile ----
        float zacc[8][4] = {};
#pragma unroll
        for (int kk = 0; kk < 64; kk += 32) {
            uint32_t kq[8][4];
#pragma unroll
            for (int nt = 0; nt < 8; nt++) {
                const uint32_t off =
                    (uint32_t)((nt * 8 + b_row) * 144 + (kk + b_koff) * 2);
                ldsm_x4(kq[nt], sb + oK_ + off);
            }
#pragma unroll
            for (int s = 0; s < 2; s++)
#pragma unroll
                for (int nt = 0; nt < 8; nt++)
                    mma16816(zacc[nt], qf[kk / 16 + s], &kq[nt][2 * s]);
        }

        // ---- sigmoid + causal mask -> Ss[i][j] (fp32) ----
        const bool diag = (tj == ti);
        float* ssp = (float*)(dsm + oSS);
#pragma unroll
        for (int nt = 0; nt < 8; nt++) {
#pragma unroll
            for (int half = 0; half < 2; half++) {
                const int i_loc = warp_m + half * 8 + r;
                float sv0 = fast_sigmoid(zacc[nt][half * 2]);
                float sv1 = fast_sigmoid(zacc[nt][half * 2 + 1]);
                if (diag && (nt * 8 + c2) >= i_loc) sv0 = 0.0f;
                if (diag && (nt * 8 + c2 + 1) >= i_loc) sv1 = 0.0f;
                *(float2*)(ssp + i_loc * 66 + nt * 8 + c2) = make_float2(sv0, sv1);
            }
        }
        __syncthreads();

        // ---- per-row suffix-product scan, emit att as fp16 ----
        if (tid < 64) {
            float acc = accp;
            const float* ssr = (float*)(dsm + oSS) + tid * 66;
            __half* ah = (__half*)(dsm + oAT) + tid * ASTR;
#pragma unroll
            for (int j = 63; j >= 0; j--) {
                const float sv = ssr[j];
                const float att = sv * acc;
                acc -= att;                       // acc *= (1 - sv)
                ah[j] = __float2half_rn(att);
            }
            accp = acc;
        }
        __syncthreads();

        // ---- O += att @ V; V x4 spans k32 per n-tile ----
#pragma unroll
        for (int kk = 0; kk < 64; kk += 32) {
            uint32_t vq[8][4];
#pragma unroll
            for (int nt = 0; nt < 8; nt++) {
                const uint32_t off =
                    (uint32_t)((nt * 8 + b_row) * 144 + (kk + b_koff) * 2);
                ldsm_x4(vq[nt], sb + oV_ + off);
            }
#pragma unroll
            for (int s = 0; s < 2; s++) {
                uint32_t av[4];
                const uint32_t offA =
                    (uint32_t)((warp_m + a_row) * 144 + (kk + s * 16 + a_koff) * 2);
                ldsm_x4(av, sb + oAT + offA);
#pragma unroll
                for (int nt = 0; nt < 8; nt++)
                    mma16816(oacc[nt], av, &vq[nt][2 * s]);
            }
        }
    }

    // ---- epilogue: write O fp16, flat [b, l, h*64+d] ----
    const int b = bh >> 5, h = bh & 31;
#pragma unroll
    for (int nt = 0; nt < 8; nt++) {
#pragma unroll
        for (int half = 0; half < 2; half++) {
            const int i = i0 + warp_m + half * 8 + r;
            const int d = nt * 8 + c2;
            const size_t adr = ((size_t)b * SEQ + i) * HID + h * HD + d;
            *(__half2*)(g_O + adr) =
                __halves2half2(__float2half_rn(oacc[nt][half * 2]),
                               __float2half_rn(oacc[nt][half * 2 + 1]));
        }
    }
}

// ======================= launch =======================
extern "C" void kernel_launch(void* const* d_in, const int* in_sizes, int n_in,
                              void* d_out, int out_size)
{
    const float* X  = (const float*)d_in[0];
    const float* Wq = (const float*)d_in[1];
    const float* Wk = (const float*)d_in[2];
    const float* Wv = (const float*)d_in[3];
    const float* Wo = (const float*)d_in[4];
    float* Out = (float*)d_out;

    cudaFuncSetAttribute(qkv_mma, cudaFuncAttributeMaxDynamicSharedMemorySize,
                         GEMM_SMEM);
    cudaFuncSetAttribute(out_mma, cudaFuncAttributeMaxDynamicSharedMemorySize,
                         GEMM_SMEM);
    cudaFuncSetAttribute(sba_attn, cudaFuncAttributeMaxDynamicSharedMemorySize,
                         ATT_SMEM);

    cvt5<<<dim3((HID * HID / 4) / 256, 1, 5), 256>>>(X, Wq, Wk, Wv, Wo);
    qkv_mma<<<dim3(HID / 128, (NBATCH * SEQ) / 128, 3), 256, GEMM_SMEM>>>();
    sba_attn<<<dim3(SEQ / 64, NBATCH * NH), 128, ATT_SMEM>>>();
    out_mma<<<dim3(HID / 128, (NBATCH * SEQ) / 128, 1), 256, GEMM_SMEM>>>(Out);
}

// round 17
// speedup vs baseline: 1.0908x; 1.0908x over previous
#include <cuda_runtime.h>
#include <cuda_fp16.h>
#include <cstdint>

#define NBATCH 2
#define SEQ    1024
#define HID    2048
#define NH     32
#define HD     64

// ======================= scratch =======================
#define QKV_ELEMS ((size_t)NBATCH * NH * SEQ * HD)
__device__ __half g_X[(size_t)NBATCH * SEQ * HID];
__device__ __half g_W[4][(size_t)HID * HID];     // q,k,v,o
__device__ __half g_Q[QKV_ELEMS];                // [b,h,l,d], pre-scaled 1/8
__device__ __half g_K[QKV_ELEMS];                // [b,h,l,d]
__device__ __half g_Vt[QKV_ELEMS];               // [b,h,d,l] transposed
__device__ __half g_O[(size_t)NBATCH * SEQ * HID];

// ======================= helpers =======================
__device__ __forceinline__ uint32_t smem_u32(const void* p) {
    uint32_t a;
    asm("{ .reg .u64 t; cvta.to.shared.u64 t, %1; cvt.u32.u64 %0, t; }"
        : "=r"(a) : "l"(p));
    return a;
}
__device__ __forceinline__ void ldsm_x4(uint32_t* r, uint32_t addr) {
    asm volatile("ldmatrix.sync.aligned.m8n8.x4.shared.b16 {%0,%1,%2,%3}, [%4];"
                 : "=r"(r[0]), "=r"(r[1]), "=r"(r[2]), "=r"(r[3]) : "r"(addr));
}
__device__ __forceinline__ void mma16816(float* c, const uint32_t* a,
                                         const uint32_t* b) {
    asm("mma.sync.aligned.m16n8k16.row.col.f32.f16.f16.f32 "
        "{%0,%1,%2,%3}, {%4,%5,%6,%7}, {%8,%9}, {%0,%1,%2,%3};"
        : "+f"(c[0]), "+f"(c[1]), "+f"(c[2]), "+f"(c[3])
        : "r"(a[0]), "r"(a[1]), "r"(a[2]), "r"(a[3]), "r"(b[0]), "r"(b[1]));
}
__device__ __forceinline__ float fast_sigmoid(float z) {
    float t;
    asm("tanh.approx.f32 %0, %1;" : "=f"(t) : "f"(z * 0.5f));
    return fmaf(0.5f, t, 0.5f);
}
__device__ __forceinline__ uint32_t pack_h2(float x, float y) {
    __half2 h = __floats2half2_rn(x, y);
    return *reinterpret_cast<uint32_t*>(&h);
}
#define CP16(dst, src) \
    asm volatile("cp.async.cg.shared.global [%0], [%1], 16;" \
                 :: "r"(dst), "l"(src) : "memory")
#define CP_COMMIT asm volatile("cp.async.commit_group;" ::: "memory")
#define CP_WAIT0  asm volatile("cp.async.wait_group 0;" ::: "memory")

// ======================= fp32 -> fp16 convert =======================
__global__ void __launch_bounds__(256)
cvt5(const float* __restrict__ X, const float* __restrict__ Wq,
     const float* __restrict__ Wk, const float* __restrict__ Wv,
     const float* __restrict__ Wo) {
    const int z = blockIdx.z;
    const float* src = (z == 0) ? X : (z == 1) ? Wq : (z == 2) ? Wk
                                   : (z == 3) ? Wv : Wo;
    __half* dst = (z == 0) ? g_X : g_W[z - 1];
    size_t i4 = ((size_t)blockIdx.x * 256 + threadIdx.x) * 4;
    float4 v = *(const float4*)(src + i4);
    ushort4 h4;
    h4.x = __half_as_ushort(__float2half_rn(v.x));
    h4.y = __half_as_ushort(__float2half_rn(v.y));
    h4.z = __half_as_ushort(__float2half_rn(v.z));
    h4.w = __half_as_ushort(__float2half_rn(v.w));
    *(ushort4*)(dst + i4) = h4;
}

// ======================= HMMA fp16 GEMM (R11/R15 config) =======================
#define GSTR  136                // fp16 elems per smem row = 272B
#define oA    0
#define oB    34816
#define STAGE_BYTES 104448       // A 128*272 + B 256*272
#define GEMM_SMEM (2 * STAGE_BYTES)

template <int MODE>
__device__ __forceinline__ void hmma_gemm_body(
    const __half* __restrict__ A, const __half* __restrict__ B,
    float* __restrict__ Cf, __half* __restrict__ Ch)
{
    extern __shared__ char dsm[];
    const uint32_t sb = smem_u32(dsm);

    const int tid = threadIdx.x;
    const int wid = tid >> 5, lane = tid & 31;
    const int warp_m = (wid >> 2) * 64;      // 0 or 64
    const int warp_n = (wid & 3) * 64;       // 0,64,128,192
    const int m0 = blockIdx.y * 128, n0 = blockIdx.x * 256;

    const uint32_t a_row = (lane & 15);
    const uint32_t a_koff = (lane >> 4) * 8;
    const uint32_t b_row = (lane & 7);
    const uint32_t b_koff = (lane >> 3) * 8; // 0,8,16,24 (k32 span)

    float acc[4][8][4] = {};

    auto load_chunk = [&](int k0, int s) {
        const uint32_t st = sb + s * STAGE_BYTES;
#pragma unroll
        for (int p = 0; p < 8; p++) {        // A: 128 rows x 16 segs
            const int flat = p * 256 + tid;
            const int row = flat >> 4, seg = flat & 15;
            const uint32_t so = (uint32_t)(row * 272 + seg * 16);
            CP16(st + oA + so, A + (size_t)(m0 + row) * HID + k0 + seg * 8);
        }
#pragma unroll
        for (int p = 0; p < 16; p++) {       // B: 256 rows x 16 segs
            const int flat = p * 256 + tid;
            const int row = flat >> 4, seg = flat & 15;
            const uint32_t so = (uint32_t)(row * 272 + seg * 16);
            CP16(st + oB + so, B + (size_t)(n0 + row) * HID + k0 + seg * 8);
        }
    };

    load_chunk(0, 0);
    CP_COMMIT;

    for (int c = 0; c < HID / 128; c++) {
        CP_WAIT0;
        __syncthreads();
        if (c < HID / 128 - 1) {
            load_chunk((c + 1) * 128, (c + 1) & 1);
            CP_COMMIT;
        }
        const uint32_t st = sb + (c & 1) * STAGE_BYTES;

#pragma unroll
        for (int kk = 0; kk < 128; kk += 32) {
            uint32_t bq[8][4];
#pragma unroll
            for (int nt = 0; nt < 8; nt++) {
                const uint32_t off =
                    (uint32_t)((warp_n + nt * 8 + b_row) * GSTR + kk + b_koff) * 2;
                ldsm_x4(bq[nt], st + oB + off);
            }
#pragma unroll
            for (int s = 0; s < 2; s++) {
                uint32_t af[4][4];
#pragma unroll
                for (int mi = 0; mi < 4; mi++) {
                    const uint32_t off =
                        (uint32_t)((warp_m + mi * 16 + a_row) * GSTR +
                                   kk + s * 16 + a_koff) * 2;
                    ldsm_x4(af[mi], st + oA + off);
                }
#pragma unroll
                for (int mi = 0; mi < 4; mi++)
#pragma unroll
                    for (int nt = 0; nt < 8; nt++)
                        mma16816(acc[mi][nt], af[mi], &bq[nt][2 * s]);
            }
        }
    }

    // epilogue
    const int tr = lane >> 2;
    const int tc = (lane & 3) * 2;

    if (MODE == 3) {
        // V: stage transposed tile [n][m] in smem, then coalesced stores.
        __syncthreads();
        __half* stg = (__half*)dsm;           // [256][128] fp16
#pragma unroll
        for (int mi = 0; mi < 4; mi++) {
#pragma unroll
            for (int ni = 0; ni < 8; ni++) {
                const int col = warp_n + ni * 8 + tc;
#pragma unroll
                for (int half = 0; half < 2; half++) {
                    const int row = warp_m + mi * 16 + half * 8 + tr;
                    stg[col * 128 + row] =
                        __float2half_rn(acc[mi][ni][half * 2]);
                    stg[(col + 1) * 128 + row] =
                        __float2half_rn(acc[mi][ni][half * 2 + 1]);
                }
            }
        }
        __syncthreads();
        const int b = m0 >> 10;
        const int l0 = m0 & (SEQ - 1);
#pragma unroll
        for (int p = 0; p < 16; p++) {
            const int flat = p * 256 + tid;
            const int nrow = flat >> 4, seg = flat & 15;
            const int h = (n0 + nrow) >> 6, d = (n0 + nrow) & 63;
            *(uint4*)(Ch + (((size_t)b * NH + h) * HD + d) * SEQ + l0 + seg * 8) =
                *(const uint4*)(stg + nrow * 128 + seg * 8);
        }
        return;
    }

#pragma unroll
    for (int mi = 0; mi < 4; mi++) {
#pragma unroll
        for (int ni = 0; ni < 8; ni++) {
            const int col = n0 + warp_n + ni * 8 + tc;
#pragma unroll
            for (int half = 0; half < 2; half++) {
                const int row = m0 + warp_m + mi * 16 + half * 8 + tr;
                float v0 = acc[mi][ni][half * 2];
                float v1 = acc[mi][ni][half * 2 + 1];
                if (MODE == 0) {
                    *(float2*)(Cf + (size_t)row * HID + col) = make_float2(v0, v1);
                } else {
                    const int b = row >> 10, l = row & (SEQ - 1);
                    const int h = col >> 6, d = col & 63;
                    if (MODE == 1) { v0 *= 0.125f; v1 *= 0.125f; }
                    const size_t adr = (((size_t)b * NH + h) * SEQ + l) * HD + d;
                    *(__half2*)(Ch + adr) =
                        __halves2half2(__float2half_rn(v0), __float2half_rn(v1));
                }
            }
        }
    }
}

__global__ void __launch_bounds__(256, 1) qkv_mma() {
    if (blockIdx.z == 0)
        hmma_gemm_body<1>(g_X, g_W[0], nullptr, g_Q);
    else if (blockIdx.z == 1)
        hmma_gemm_body<2>(g_X, g_W[1], nullptr, g_K);
    else
        hmma_gemm_body<3>(g_X, g_W[2], nullptr, g_Vt);
}

__global__ void __launch_bounds__(256, 1) out_mma(float* Out) {
    hmma_gemm_body<0>(g_O, g_W[3], Out, nullptr);
}

// ======================= stick-breaking attention (register scan) =======================
// 64 queries/CTA, 4 warps x 16 rows. z fragments double as att A-fragments:
// in-register sigmoid + quad-shfl suffix-product scan, no SS/AT smem, 2 barriers.
#define oQ   0
#define oK_  9216
#define oV_  18432
#define ATT_SMEM 27648

__global__ void __launch_bounds__(128, 4) sba_attn()
{
    extern __shared__ char dsm[];
    const uint32_t sb = smem_u32(dsm);

    const int tid = threadIdx.x;
    const int wid = tid >> 5, lane = tid & 31;
    const int warp_m = wid * 16;
    const int ti = (gridDim.x - 1) - blockIdx.x;   // heavy blocks first
    const int bh = blockIdx.y;
    const int i0 = ti * 64;

    const size_t base = (size_t)bh * SEQ * HD;
    const __half* Q_g  = g_Q + base + (size_t)i0 * HD;
    const __half* K_g  = g_K + base;
    const __half* Vt_g = g_Vt + base;              // [d][l]

    // ---- load Q tile (64x64 fp16) ----
#pragma unroll
    for (int t = 0; t < 4; t++) {
        const int flat = t * 128 + tid;
        const int row = flat >> 3, seg = flat & 7;
        const uint32_t off = (uint32_t)(row * 144 + seg * 16);
        CP16(sb + oQ + off, Q_g + row * HD + seg * 8);
    }
    CP_COMMIT;
    CP_WAIT0;
    __syncthreads();

    const uint32_t a_row = lane & 15;
    const uint32_t a_koff = (lane >> 4) * 8;
    const uint32_t b_row = lane & 7;
    const uint32_t b_koff = (lane >> 3) * 8;       // k32 span

    uint32_t qf[4][4];
#pragma unroll
    for (int kk = 0; kk < 4; kk++) {
        const uint32_t off =
            (uint32_t)((warp_m + a_row) * 144 + (kk * 16 + a_koff) * 2);
        ldsm_x4(qf[kk], sb + oQ + off);
    }

    float oacc[8][4] = {};
    float carry_a = 1.0f, carry_b = 1.0f;          // per-row suffix carries
    const int r = lane >> 2;
    const int tq = lane & 3;
    const int c2 = tq * 2;

    for (int tj = ti; tj >= 0; tj--) {
        const int j0 = tj * 64;
        __syncthreads();                           // prev V reads done

        // ---- load K [j][d] and Vt [d][j0+j] tiles ----
#pragma unroll
        for (int t = 0; t < 4; t++) {
            const int flat = t * 128 + tid;
            const int row = flat >> 3, seg = flat & 7;
            const uint32_t off = (uint32_t)(row * 144 + seg * 16);
            CP16(sb + oK_ + off, K_g + (size_t)(j0 + row) * HD + seg * 8);
            CP16(sb + oV_ + off, Vt_g + (size_t)row * SEQ + j0 + seg * 8);
        }
        CP_COMMIT;
        CP_WAIT0;
        __syncthreads();

        // ---- z = Q K^T (Q pre-scaled); K x4 spans k32 per n-tile ----
        float zacc[8][4] = {};
#pragma unroll
        for (int kk = 0; kk < 64; kk += 32) {
            uint32_t kq[8][4];
#pragma unroll
            for (int nt = 0; nt < 8; nt++) {
                const uint32_t off =
                    (uint32_t)((nt * 8 + b_row) * 144 + (kk + b_koff) * 2);
                ldsm_x4(kq[nt], sb + oK_ + off);
            }
#pragma unroll
            for (int s = 0; s < 2; s++)
#pragma unroll
                for (int nt = 0; nt < 8; nt++)
                    mma16816(zacc[nt], qf[kk / 16 + s], &kq[nt][2 * s]);
        }

        // ---- sigmoid + causal mask, in registers ----
        const bool diag = (tj == ti);
#pragma unroll
        for (int nt = 0; nt < 8; nt++) {
#pragma unroll
            for (int e = 0; e < 4; e++) {
                float sv = fast_sigmoid(zacc[nt][e]);
                if (diag) {
                    const int i_loc = warp_m + (e >> 1) * 8 + r;
                    const int j_loc = nt * 8 + c2 + (e & 1);
                    if (j_loc >= i_loc) sv = 0.0f;   // j0+j >= i0+i <=> j>=i (tj==ti)
                }
                zacc[nt][e] = sv;
            }
        }

        // ---- register suffix-product scan (quad shfl), nt descending ----
        {
            float Sa = 1.0f, Sb = 1.0f;
#pragma unroll
            for (int nt = 7; nt >= 0; nt--) {
                const float s0 = zacc[nt][0], s1 = zacc[nt][1];
                const float s2 = zacc[nt][2], s3 = zacc[nt][3];
                const float ua = (1.0f - s0) * (1.0f - s1);
                const float ub = (1.0f - s2) * (1.0f - s3);
                const float ua1 = __shfl_xor_sync(0xffffffffu, ua, 1);
                const float ua2 = __shfl_xor_sync(0xffffffffu, ua, 2);
                const float ua3 = __shfl_xor_sync(0xffffffffu, ua, 3);
                const float ub1 = __shfl_xor_sync(0xffffffffu, ub, 1);
                const float ub2 = __shfl_xor_sync(0xffffffffu, ub, 2);
                const float ub3 = __shfl_xor_sync(0xffffffffu, ub, 3);
                // suffix over quad lanes with higher tq (higher j within nt)
                const float Wa = (tq == 0) ? ua1 * ua2 * ua3
                               : (tq == 1) ? ua2 * ua3
                               : (tq == 2) ? ua1 : 1.0f;
                const float Wb = (tq == 0) ? ub1 * ub2 * ub3
                               : (tq == 1) ? ub2 * ub3
                               : (tq == 2) ? ub1 : 1.0f;
                const float suf1a = carry_a * Sa * Wa;
                const float suf1b = carry_b * Sb * Wb;
                zacc[nt][1] = s1 * suf1a;
                zacc[nt][0] = s0 * suf1a * (1.0f - s1);
                zacc[nt][3] = s3 * suf1b;
                zacc[nt][2] = s2 * suf1b * (1.0f - s3);
                Sa *= ua * ua1 * ua2 * ua3;        // full-quad group product
                Sb *= ub * ub1 * ub2 * ub3;
            }
            carry_a *= Sa;
            carry_b *= Sb;
        }

        // ---- O += att @ V; att packed from registers (A-fragment layout) ----
#pragma unroll
        for (int kk = 0; kk < 64; kk += 32) {
            uint32_t vq[8][4];
#pragma unroll
            for (int nt = 0; nt < 8; nt++) {
                const uint32_t off =
                    (uint32_t)((nt * 8 + b_row) * 144 + (kk + b_koff) * 2);
                ldsm_x4(vq[nt], sb + oV_ + off);
            }
#pragma unroll
            for (int s = 0; s < 2; s++) {
                const int g = kk / 16 + s;         // k16 group 0..3
                uint32_t af[4];
                af[0] = pack_h2(zacc[2 * g][0], zacc[2 * g][1]);       // row r,  k 0-7
                af[1] = pack_h2(zacc[2 * g][2], zacc[2 * g][3]);       // row r+8
                af[2] = pack_h2(zacc[2 * g + 1][0], zacc[2 * g + 1][1]); // row r,  k 8-15
                af[3] = pack_h2(zacc[2 * g + 1][2], zacc[2 * g + 1][3]); // row r+8
#pragma unroll
                for (int nt = 0; nt < 8; nt++)
                    mma16816(oacc[nt], af, &vq[nt][2 * s]);
            }
        }
    }

    // ---- epilogue: write O fp16, flat [b, l, h*64+d] ----
    const int b = bh >> 5, h = bh & 31;
#pragma unroll
    for (int nt = 0; nt < 8; nt++) {
#pragma unroll
        for (int half = 0; half < 2; half++) {
            const int i = i0 + warp_m + half * 8 + r;
            const int d = nt * 8 + c2;
            const size_t adr = ((size_t)b * SEQ + i) * HID + h * HD + d;
            *(__half2*)(g_O + adr) =
                __halves2half2(__float2half_rn(oacc[nt][half * 2]),
                               __float2half_rn(oacc[nt][half * 2 + 1]));
        }
    }
}

// ======================= launch =======================
extern "C" void kernel_launch(void* const* d_in, const int* in_sizes, int n_in,
                              void* d_out, int out_size)
{
    const float* X  = (const float*)d_in[0];
    const float* Wq = (const float*)d_in[1];
    const float* Wk = (const float*)d_in[2];
    const float* Wv = (const float*)d_in[3];
    const float* Wo = (const float*)d_in[4];
    float* Out = (float*)d_out;

    cudaFuncSetAttribute(qkv_mma, cudaFuncAttributeMaxDynamicSharedMemorySize,
                         GEMM_SMEM);
    cudaFuncSetAttribute(out_mma, cudaFuncAttributeMaxDynamicSharedMemorySize,
                         GEMM_SMEM);
    cudaFuncSetAttribute(sba_attn, cudaFuncAttributeMaxDynamicSharedMemorySize,
                         ATT_SMEM);

    cvt5<<<dim3((HID * HID / 4) / 256, 1, 5), 256>>>(X, Wq, Wk, Wv, Wo);
    qkv_mma<<<dim3(HID / 256, (NBATCH * SEQ) / 128, 3), 256, GEMM_SMEM>>>();
    sba_attn<<<dim3(SEQ / 64, NBATCH * NH), 128, ATT_SMEM>>>();
    out_mma<<<dim3(HID / 256, (NBATCH * SEQ) / 128, 1), 256, GEMM_SMEM>>>(Out);
}